// round 10
// baseline (speedup 1.0000x reference)
#include <cuda_runtime.h>
#include <cuda_bf16.h>
#include <math.h>

#define NN 100000
#define EMAX 1700000
#define NEG_SLOPE 0.2f

typedef unsigned long long u64;

// ---------------- scratch (device globals) ----------------
__device__ __align__(16) float g_h1[NN * 64];
__device__ __align__(16) float g_as1[NN * 8];
__device__ __align__(16) float g_ad1[NN * 8];
__device__ __align__(16) float g_hmid[NN * 64];
__device__ __align__(16) float g_h2[NN * 128];
__device__ __align__(16) float g_as2[NN];
__device__ __align__(16) float g_ad2[NN];
// CSR by destination
__device__ int g_cnt[NN];
__device__ int g_off[NN + 1];
__device__ int g_bsum[128];
__device__ int g_csr[EMAX];

// ---------------- helpers ----------------
__device__ __forceinline__ float leaky(float v) {
    return v > 0.0f ? v : NEG_SLOPE * v;
}
__device__ __forceinline__ void load_edge(const int* __restrict__ ei, int E,
                                          int idx, int& s, int& d) {
    if (idx < E) { s = ei[idx]; d = ei[E + idx]; }
    else         { s = d = idx - E; }
}
__device__ __forceinline__ u64 pack2(float v) {
    u64 r; asm("mov.b64 %0, {%1, %1};" : "=l"(r) : "f"(v)); return r;
}
__device__ __forceinline__ void ffma2(u64& acc, u64 a, u64 b) {
    asm("fma.rn.f32x2 %0, %1, %2, %3;" : "=l"(acc) : "l"(a), "l"(b), "l"(acc));
}
__device__ __forceinline__ float2 up2(u64 v) { return *(float2*)&v; }

// ---------------- CSR build ----------------
__global__ __launch_bounds__(256)
void hist_kernel(const int* __restrict__ ei, int E, int Etot) {
    int idx = blockIdx.x * blockDim.x + threadIdx.x;
    if (idx >= Etot) return;
    int s, d; load_edge(ei, E, idx, s, d);
    atomicAdd(&g_cnt[d], 1);
}

__global__ __launch_bounds__(256)
void scan1_kernel(int n) {
    __shared__ int wsum[8];
    int blk = blockIdx.x;
    int tid = threadIdx.x;
    int i = blk * 1024 + tid * 4;
    int a0 = (i + 0 < n) ? g_cnt[i + 0] : 0;
    int a1 = (i + 1 < n) ? g_cnt[i + 1] : 0;
    int a2 = (i + 2 < n) ? g_cnt[i + 2] : 0;
    int a3 = (i + 3 < n) ? g_cnt[i + 3] : 0;
    int tsum = a0 + a1 + a2 + a3;
    int lane = tid & 31, wid = tid >> 5;
    int sc = tsum;
#pragma unroll
    for (int off = 1; off < 32; off <<= 1) {
        int t = __shfl_up_sync(0xFFFFFFFFu, sc, off);
        if (lane >= off) sc += t;
    }
    if (lane == 31) wsum[wid] = sc;
    __syncthreads();
    if (wid == 0) {
        int ws = (lane < 8) ? wsum[lane] : 0;
#pragma unroll
        for (int off = 1; off < 8; off <<= 1) {
            int t = __shfl_up_sync(0xFFFFFFFFu, ws, off);
            if (lane >= off) ws += t;
        }
        if (lane < 8) wsum[lane] = ws;
    }
    __syncthreads();
    int excl = sc - tsum + (wid > 0 ? wsum[wid - 1] : 0);
    if (i + 0 < n) g_off[i + 0] = excl;
    if (i + 1 < n) g_off[i + 1] = excl + a0;
    if (i + 2 < n) g_off[i + 2] = excl + a0 + a1;
    if (i + 3 < n) g_off[i + 3] = excl + a0 + a1 + a2;
    if (tid == 255) g_bsum[blk] = excl + tsum;
}

__global__ void scan2_kernel(int nb, int n) {
    int lane = threadIdx.x & 31;
    int v[4]; int s = 0;
#pragma unroll
    for (int i = 0; i < 4; i++) {
        int idx = lane * 4 + i;
        v[i] = (idx < nb) ? g_bsum[idx] : 0;
        s += v[i];
    }
    int sc = s;
#pragma unroll
    for (int off = 1; off < 32; off <<= 1) {
        int t = __shfl_up_sync(0xFFFFFFFFu, sc, off);
        if (lane >= off) sc += t;
    }
    int run = sc - s;
#pragma unroll
    for (int i = 0; i < 4; i++) {
        int idx = lane * 4 + i;
        int t = v[i];
        if (idx < nb) g_bsum[idx] = run;
        run += t;
    }
    if (lane == 31) g_off[n] = run;
}

__global__ __launch_bounds__(256)
void scan3_kernel(int n) {
    int i = blockIdx.x * blockDim.x + threadIdx.x;
    if (i < n) g_off[i] += g_bsum[i >> 10];
}

__global__ __launch_bounds__(256)
void scatter_kernel(const int* __restrict__ ei, int E, int Etot) {
    int idx = blockIdx.x * blockDim.x + threadIdx.x;
    if (idx >= Etot) return;
    int s, d; load_edge(ei, E, idx, s, d);
    int pos = g_off[d] + atomicAdd(&g_cnt[d], 1);
    g_csr[pos] = s;
}

// ---------------- GEMM (+ optional fused alpha1), 2-stage double-buffered ----
// BM=128, BN=64, BK=16, 256 threads, 4 row-pairs x 4 cols per thread, FFMA2.
// One __syncthreads per K-tile; LDG prefetch overlaps compute.
template<bool FUSE_ALPHA>
__global__ __launch_bounds__(256)
void gemm_kernel(const float* __restrict__ A, const float* __restrict__ B,
                 float* __restrict__ C, int M, int K, int Ncol,
                 const float* __restrict__ att_s, const float* __restrict__ att_d) {
    __shared__ float As[2][16][132];
    __shared__ float Bs[2][16][68];
    const int bm = blockIdx.x * 128;
    const int bn = blockIdx.y * 64;
    const int tid = threadIdx.x;
    const int tx = tid & 15;
    const int ty = tid >> 4;

    const int a_row  = tid >> 2;
    const int a_col4 = (tid & 3) * 4;
    const int b_row  = tid >> 4;
    const int b_col4 = (tid & 15) * 4;

    const int grow0 = bm + a_row;
    const int grow1 = bm + a_row + 64;

    u64 acc[4][4];
#pragma unroll
    for (int p = 0; p < 4; p++)
#pragma unroll
        for (int j = 0; j < 4; j++) acc[p][j] = 0ULL;

    // preload tile 0 -> regs -> stage 0
    float4 pa0 = make_float4(0.f,0.f,0.f,0.f), pa1 = pa0, pb;
    if (grow0 < M) pa0 = *(const float4*)&A[(size_t)grow0 * K + a_col4];
    if (grow1 < M) pa1 = *(const float4*)&A[(size_t)grow1 * K + a_col4];
    pb = *(const float4*)&B[(size_t)b_row * Ncol + bn + b_col4];

    As[0][a_col4 + 0][a_row] = pa0.x;
    As[0][a_col4 + 1][a_row] = pa0.y;
    As[0][a_col4 + 2][a_row] = pa0.z;
    As[0][a_col4 + 3][a_row] = pa0.w;
    As[0][a_col4 + 0][a_row + 64] = pa1.x;
    As[0][a_col4 + 1][a_row + 64] = pa1.y;
    As[0][a_col4 + 2][a_row + 64] = pa1.z;
    As[0][a_col4 + 3][a_row + 64] = pa1.w;
    *(float4*)&Bs[0][b_row][b_col4] = pb;
    __syncthreads();

    const int ntiles = K >> 4;
    for (int t = 0; t < ntiles; t++) {
        const int st = t & 1;
        const int kn = (t + 1) << 4;
        if (kn < K) {   // prefetch next tile; latency hidden under compute
            if (grow0 < M) pa0 = *(const float4*)&A[(size_t)grow0 * K + kn + a_col4];
            if (grow1 < M) pa1 = *(const float4*)&A[(size_t)grow1 * K + kn + a_col4];
            pb = *(const float4*)&B[(size_t)(kn + b_row) * Ncol + bn + b_col4];
        }

#pragma unroll
        for (int kk = 0; kk < 16; kk++) {
            ulonglong2 A01 = *(const ulonglong2*)&As[st][kk][ty * 8];
            ulonglong2 A23 = *(const ulonglong2*)&As[st][kk][ty * 8 + 4];
            float4 b = *(const float4*)&Bs[st][kk][tx * 4];
            u64 b0 = pack2(b.x), b1 = pack2(b.y), b2 = pack2(b.z), b3 = pack2(b.w);
            ffma2(acc[0][0], A01.x, b0); ffma2(acc[0][1], A01.x, b1);
            ffma2(acc[0][2], A01.x, b2); ffma2(acc[0][3], A01.x, b3);
            ffma2(acc[1][0], A01.y, b0); ffma2(acc[1][1], A01.y, b1);
            ffma2(acc[1][2], A01.y, b2); ffma2(acc[1][3], A01.y, b3);
            ffma2(acc[2][0], A23.x, b0); ffma2(acc[2][1], A23.x, b1);
            ffma2(acc[2][2], A23.x, b2); ffma2(acc[2][3], A23.x, b3);
            ffma2(acc[3][0], A23.y, b0); ffma2(acc[3][1], A23.y, b1);
            ffma2(acc[3][2], A23.y, b2); ffma2(acc[3][3], A23.y, b3);
        }

        if (kn < K) {   // store prefetched tile into the other stage
            const int sn = st ^ 1;
            As[sn][a_col4 + 0][a_row] = pa0.x;
            As[sn][a_col4 + 1][a_row] = pa0.y;
            As[sn][a_col4 + 2][a_row] = pa0.z;
            As[sn][a_col4 + 3][a_row] = pa0.w;
            As[sn][a_col4 + 0][a_row + 64] = pa1.x;
            As[sn][a_col4 + 1][a_row + 64] = pa1.y;
            As[sn][a_col4 + 2][a_row + 64] = pa1.z;
            As[sn][a_col4 + 3][a_row + 64] = pa1.w;
            *(float4*)&Bs[sn][b_row][b_col4] = pb;
            __syncthreads();
        }
    }

#pragma unroll
    for (int p = 0; p < 4; p++) {
        float2 f0 = up2(acc[p][0]);
        float2 f1 = up2(acc[p][1]);
        float2 f2 = up2(acc[p][2]);
        float2 f3 = up2(acc[p][3]);
        int r0 = bm + ty * 8 + 2 * p;
        if (r0 < M)
            *(float4*)&C[(size_t)r0 * Ncol + bn + tx * 4] =
                make_float4(f0.x, f1.x, f2.x, f3.x);
        if (r0 + 1 < M)
            *(float4*)&C[(size_t)(r0 + 1) * Ncol + bn + tx * 4] =
                make_float4(f0.y, f1.y, f2.y, f3.y);
    }

    if (FUSE_ALPHA) {
        float4 asv = ((const float4*)att_s)[tx];
        float4 adv = ((const float4*)att_d)[tx];
        u64 sx = pack2(asv.x), sy = pack2(asv.y), sz = pack2(asv.z), sw = pack2(asv.w);
        u64 dx = pack2(adv.x), dy = pack2(adv.y), dz = pack2(adv.z), dw = pack2(adv.w);
        int h = tx >> 1;
#pragma unroll
        for (int p = 0; p < 4; p++) {
            u64 ps = 0ULL, pd = 0ULL;
            ffma2(ps, acc[p][0], sx); ffma2(ps, acc[p][1], sy);
            ffma2(ps, acc[p][2], sz); ffma2(ps, acc[p][3], sw);
            ffma2(pd, acc[p][0], dx); ffma2(pd, acc[p][1], dy);
            ffma2(pd, acc[p][2], dz); ffma2(pd, acc[p][3], dw);
            u64 os = __shfl_xor_sync(0xFFFFFFFFu, ps, 1);
            u64 od = __shfl_xor_sync(0xFFFFFFFFu, pd, 1);
            float2 a = up2(ps), b = up2(os), c = up2(pd), d = up2(od);
            float2 rs = make_float2(a.x + b.x, a.y + b.y);
            float2 rd = make_float2(c.x + d.x, c.y + d.y);
            if ((tx & 1) == 0) {
                int r0 = bm + ty * 8 + 2 * p;
                if (r0 < M)     { g_as1[r0 * 8 + h] = rs.x; g_ad1[r0 * 8 + h] = rd.x; }
                if (r0 + 1 < M) { g_as1[(r0 + 1) * 8 + h] = rs.y; g_ad1[(r0 + 1) * 8 + h] = rd.y; }
            }
        }
    }
}

// ---------------- layer2 alpha ----------------
__global__ __launch_bounds__(256)
void alpha2_kernel(const float* __restrict__ att_src, const float* __restrict__ att_dst,
                   int nnodes) {
    int gid = blockIdx.x * blockDim.x + threadIdx.x;
    int n = gid >> 5;
    int lane = gid & 31;
    if (n >= nnodes) return;
    float4 v = *(const float4*)&g_h2[(size_t)n * 128 + lane * 4];
    float4 a = ((const float4*)att_src)[lane];
    float4 b = ((const float4*)att_dst)[lane];
    float ss = v.x * a.x + v.y * a.y + v.z * a.z + v.w * a.w;
    float dd = v.x * b.x + v.y * b.y + v.z * b.z + v.w * b.w;
#pragma unroll
    for (int off = 16; off > 0; off >>= 1) {
        ss += __shfl_xor_sync(0xFFFFFFFFu, ss, off);
        dd += __shfl_xor_sync(0xFFFFFFFFu, dd, off);
    }
    if (lane == 0) { g_as2[n] = ss; g_ad2[n] = dd; }
}

// ---------------- aggregations: warp/node, 4-edge unrolled gathers ------------
__global__ __launch_bounds__(256)
void agg1_kernel(const float* __restrict__ b1, int nnodes) {
    int gw = (blockIdx.x * 256 + threadIdx.x) >> 5;
    int lane = threadIdx.x & 31;
    if (gw >= nnodes) return;
    int h = lane >> 2;
    float ad = g_ad1[gw * 8 + h];
    int beg = g_off[gw], end = g_off[gw + 1];
    float ax = 0.f, ay = 0.f, denom = 0.f;
    int j = beg;
    for (; j + 4 <= end; j += 4) {
        int s0 = g_csr[j], s1 = g_csr[j + 1], s2 = g_csr[j + 2], s3 = g_csr[j + 3];
        float e0 = g_as1[s0 * 8 + h], e1 = g_as1[s1 * 8 + h];
        float e2 = g_as1[s2 * 8 + h], e3 = g_as1[s3 * 8 + h];
        float2 v0 = *(const float2*)&g_h1[s0 * 64 + lane * 2];
        float2 v1 = *(const float2*)&g_h1[s1 * 64 + lane * 2];
        float2 v2 = *(const float2*)&g_h1[s2 * 64 + lane * 2];
        float2 v3 = *(const float2*)&g_h1[s3 * 64 + lane * 2];
        float w0 = __expf(leaky(e0 + ad));
        float w1 = __expf(leaky(e1 + ad));
        float w2 = __expf(leaky(e2 + ad));
        float w3 = __expf(leaky(e3 + ad));
        ax += w0 * v0.x + w1 * v1.x + w2 * v2.x + w3 * v3.x;
        ay += w0 * v0.y + w1 * v1.y + w2 * v2.y + w3 * v3.y;
        denom += (w0 + w1) + (w2 + w3);
    }
    for (; j < end; j++) {
        int s = g_csr[j];
        float w = __expf(leaky(g_as1[s * 8 + h] + ad));
        float2 v = *(const float2*)&g_h1[s * 64 + lane * 2];
        ax += w * v.x; ay += w * v.y; denom += w;
    }
    float inv = 1.0f / denom;
    int c = lane * 2;
    float o0 = ax * inv + b1[c];
    float o1 = ay * inv + b1[c + 1];
    o0 = o0 > 0.f ? o0 : expm1f(o0);
    o1 = o1 > 0.f ? o1 : expm1f(o1);
    *(float2*)&g_hmid[gw * 64 + c] = make_float2(o0, o1);
}

__global__ __launch_bounds__(256)
void agg2_kernel(const float* __restrict__ b2, float* __restrict__ out, int nnodes) {
    int gw = (blockIdx.x * 256 + threadIdx.x) >> 5;
    int lane = threadIdx.x & 31;
    if (gw >= nnodes) return;
    float ad = g_ad2[gw];
    int beg = g_off[gw], end = g_off[gw + 1];
    float4 acc = make_float4(0.f, 0.f, 0.f, 0.f);
    float denom = 0.f;
    int j = beg;
    for (; j + 4 <= end; j += 4) {
        int s0 = g_csr[j], s1 = g_csr[j + 1], s2 = g_csr[j + 2], s3 = g_csr[j + 3];
        float e0 = g_as2[s0], e1 = g_as2[s1], e2 = g_as2[s2], e3 = g_as2[s3];
        float4 v0 = *(const float4*)&g_h2[(size_t)s0 * 128 + lane * 4];
        float4 v1 = *(const float4*)&g_h2[(size_t)s1 * 128 + lane * 4];
        float4 v2 = *(const float4*)&g_h2[(size_t)s2 * 128 + lane * 4];
        float4 v3 = *(const float4*)&g_h2[(size_t)s3 * 128 + lane * 4];
        float w0 = __expf(leaky(e0 + ad));
        float w1 = __expf(leaky(e1 + ad));
        float w2 = __expf(leaky(e2 + ad));
        float w3 = __expf(leaky(e3 + ad));
        acc.x += w0 * v0.x + w1 * v1.x + w2 * v2.x + w3 * v3.x;
        acc.y += w0 * v0.y + w1 * v1.y + w2 * v2.y + w3 * v3.y;
        acc.z += w0 * v0.z + w1 * v1.z + w2 * v2.z + w3 * v3.z;
        acc.w += w0 * v0.w + w1 * v1.w + w2 * v2.w + w3 * v3.w;
        denom += (w0 + w1) + (w2 + w3);
    }
    for (; j < end; j++) {
        int s = g_csr[j];
        float w = __expf(leaky(g_as2[s] + ad));
        float4 v = *(const float4*)&g_h2[(size_t)s * 128 + lane * 4];
        acc.x += w * v.x; acc.y += w * v.y; acc.z += w * v.z; acc.w += w * v.w;
        denom += w;
    }
    float inv = 1.0f / denom;
    float4 bb = ((const float4*)b2)[lane];
    float4 o = make_float4(acc.x * inv + bb.x, acc.y * inv + bb.y,
                           acc.z * inv + bb.z, acc.w * inv + bb.w);
    *(float4*)&out[(size_t)gw * 128 + lane * 4] = o;
}

// ---------------- launcher ----------------
static cudaStream_t g_side = nullptr;
static cudaEvent_t  g_ev_fork = nullptr, g_ev_csr = nullptr;

extern "C" void kernel_launch(void* const* d_in, const int* in_sizes, int n_in,
                              void* d_out, int out_size) {
    const float* x        = (const float*)d_in[0];
    const int*   ei       = (const int*)d_in[1];
    const float* W1       = (const float*)d_in[2];
    const float* att_src1 = (const float*)d_in[3];
    const float* att_dst1 = (const float*)d_in[4];
    const float* b1       = (const float*)d_in[5];
    const float* W2       = (const float*)d_in[6];
    const float* att_src2 = (const float*)d_in[7];
    const float* att_dst2 = (const float*)d_in[8];
    const float* b2       = (const float*)d_in[9];
    float* out = (float*)d_out;

    const int nnodes = in_sizes[0] / 512;
    const int E      = in_sizes[1] / 2;
    const int Etot   = E + nnodes;
    const int T = 256;
    const int NB = (nnodes + 1023) / 1024;

    if (!g_side) {
        cudaStreamCreateWithFlags(&g_side, cudaStreamNonBlocking);
        cudaEventCreateWithFlags(&g_ev_fork, cudaEventDisableTiming);
        cudaEventCreateWithFlags(&g_ev_csr,  cudaEventDisableTiming);
    }

    void* pcnt; cudaGetSymbolAddress(&pcnt, g_cnt);
    float *h1_ptr, *hmid_ptr, *h2_ptr;
    cudaGetSymbolAddress((void**)&h1_ptr, g_h1);
    cudaGetSymbolAddress((void**)&hmid_ptr, g_hmid);
    cudaGetSymbolAddress((void**)&h2_ptr, g_h2);

    // gemm1 stays at kernel-launch #4 for ncu capture.
    cudaEventRecord(g_ev_fork, 0);
    cudaStreamWaitEvent(g_side, g_ev_fork, 0);

    cudaMemsetAsync(pcnt, 0, (size_t)nnodes * 4, g_side);
    hist_kernel<<<(Etot + T - 1) / T, T, 0, g_side>>>(ei, E, Etot);      // k1
    scan1_kernel<<<NB, T, 0, g_side>>>(nnodes);                          // k2
    scan2_kernel<<<1, 32, 0, g_side>>>(NB, nnodes);                      // k3

    dim3 g1grid((nnodes + 127) / 128, 1);
    gemm_kernel<true><<<g1grid, T>>>(x, W1, h1_ptr, nnodes, 512, 64,     // k4 (profiled)
                                     att_src1, att_dst1);

    scan3_kernel<<<(nnodes + T - 1) / T, T, 0, g_side>>>(nnodes);        // k5
    cudaMemsetAsync(pcnt, 0, (size_t)nnodes * 4, g_side);
    scatter_kernel<<<(Etot + T - 1) / T, T, 0, g_side>>>(ei, E, Etot);   // k6
    cudaEventRecord(g_ev_csr, g_side);

    cudaStreamWaitEvent(0, g_ev_csr, 0);
    agg1_kernel<<<((size_t)nnodes * 32 + T - 1) / T, T>>>(b1, nnodes);   // k7

    dim3 g2grid((nnodes + 127) / 128, 2);
    gemm_kernel<false><<<g2grid, T>>>(hmid_ptr, W2, h2_ptr, nnodes, 64, 128,  // k8
                                      nullptr, nullptr);
    alpha2_kernel<<<((size_t)nnodes * 32 + T - 1) / T, T>>>(att_src2, att_dst2, nnodes); // k9
    agg2_kernel<<<((size_t)nnodes * 32 + T - 1) / T, T>>>(b2, out, nnodes);   // k10
}

// round 13
// speedup vs baseline: 1.1388x; 1.1388x over previous
#include <cuda_runtime.h>
#include <cuda_bf16.h>
#include <cstdint>
#include <math.h>

#define NN 100000
#define EMAX 1700000
#define NEG_SLOPE 0.2f

typedef unsigned long long u64;
typedef unsigned int u32;

// ---------------- scratch (device globals) ----------------
__device__ __align__(16) float g_h1[NN * 64];
__device__ __align__(16) float g_as1[NN * 8];
__device__ __align__(16) float g_ad1[NN * 8];
__device__ __align__(16) float g_hmid[NN * 64];
__device__ __align__(16) float g_h2[NN * 128];
__device__ __align__(16) float g_as2[NN];
__device__ __align__(16) float g_ad2[NN];
// W1 transposed + bf16 hi/lo split: [64 n][512 k]
__device__ __align__(16) __nv_bfloat16 g_w1h[64 * 512];
__device__ __align__(16) __nv_bfloat16 g_w1l[64 * 512];
// CSR by destination
__device__ int g_cnt[NN];
__device__ int g_off[NN + 1];
__device__ int g_bsum[128];
__device__ int g_csr[EMAX];

// ---------------- helpers ----------------
__device__ __forceinline__ float leaky(float v) {
    return v > 0.0f ? v : NEG_SLOPE * v;
}
__device__ __forceinline__ void load_edge(const int* __restrict__ ei, int E,
                                          int idx, int& s, int& d) {
    if (idx < E) { s = ei[idx]; d = ei[E + idx]; }
    else         { s = d = idx - E; }
}
__device__ __forceinline__ u64 pack2(float v) {
    u64 r; asm("mov.b64 %0, {%1, %1};" : "=l"(r) : "f"(v)); return r;
}
__device__ __forceinline__ void ffma2(u64& acc, u64 a, u64 b) {
    asm("fma.rn.f32x2 %0, %1, %2, %3;" : "=l"(acc) : "l"(a), "l"(b), "l"(acc));
}
__device__ __forceinline__ float2 up2(u64 v) { return *(float2*)&v; }

__device__ __forceinline__ u32 smem_u32(const void* p) {
    u32 a;
    asm("{ .reg .u64 t; cvta.to.shared.u64 t, %1; cvt.u32.u64 %0, t; }" : "=r"(a) : "l"(p));
    return a;
}
__device__ __forceinline__ void ldm_x4(u32* r, u32 addr) {
    asm volatile("ldmatrix.sync.aligned.m8n8.x4.shared.b16 {%0,%1,%2,%3}, [%4];"
                 : "=r"(r[0]), "=r"(r[1]), "=r"(r[2]), "=r"(r[3]) : "r"(addr));
}
__device__ __forceinline__ void mma_bf16(float* d, const u32* a, const u32* b) {
    asm volatile(
        "mma.sync.aligned.m16n8k16.row.col.f32.bf16.bf16.f32 "
        "{%0,%1,%2,%3}, {%4,%5,%6,%7}, {%8,%9}, {%0,%1,%2,%3};"
        : "+f"(d[0]), "+f"(d[1]), "+f"(d[2]), "+f"(d[3])
        : "r"(a[0]), "r"(a[1]), "r"(a[2]), "r"(a[3]), "r"(b[0]), "r"(b[1]));
}

// ---------------- CSR build ----------------
__global__ __launch_bounds__(256)
void hist_kernel(const int* __restrict__ ei, int E, int Etot) {
    int idx = blockIdx.x * blockDim.x + threadIdx.x;
    if (idx >= Etot) return;
    int s, d; load_edge(ei, E, idx, s, d);
    atomicAdd(&g_cnt[d], 1);
}

__global__ __launch_bounds__(256)
void scan1_kernel(int n) {
    __shared__ int wsum[8];
    int blk = blockIdx.x;
    int tid = threadIdx.x;
    int i = blk * 1024 + tid * 4;
    int a0 = (i + 0 < n) ? g_cnt[i + 0] : 0;
    int a1 = (i + 1 < n) ? g_cnt[i + 1] : 0;
    int a2 = (i + 2 < n) ? g_cnt[i + 2] : 0;
    int a3 = (i + 3 < n) ? g_cnt[i + 3] : 0;
    int tsum = a0 + a1 + a2 + a3;
    int lane = tid & 31, wid = tid >> 5;
    int sc = tsum;
#pragma unroll
    for (int off = 1; off < 32; off <<= 1) {
        int t = __shfl_up_sync(0xFFFFFFFFu, sc, off);
        if (lane >= off) sc += t;
    }
    if (lane == 31) wsum[wid] = sc;
    __syncthreads();
    if (wid == 0) {
        int ws = (lane < 8) ? wsum[lane] : 0;
#pragma unroll
        for (int off = 1; off < 8; off <<= 1) {
            int t = __shfl_up_sync(0xFFFFFFFFu, ws, off);
            if (lane >= off) ws += t;
        }
        if (lane < 8) wsum[lane] = ws;
    }
    __syncthreads();
    int excl = sc - tsum + (wid > 0 ? wsum[wid - 1] : 0);
    if (i + 0 < n) g_off[i + 0] = excl;
    if (i + 1 < n) g_off[i + 1] = excl + a0;
    if (i + 2 < n) g_off[i + 2] = excl + a0 + a1;
    if (i + 3 < n) g_off[i + 3] = excl + a0 + a1 + a2;
    if (tid == 255) g_bsum[blk] = excl + tsum;
}

__global__ void scan2_kernel(int nb, int n) {
    int lane = threadIdx.x & 31;
    int v[4]; int s = 0;
#pragma unroll
    for (int i = 0; i < 4; i++) {
        int idx = lane * 4 + i;
        v[i] = (idx < nb) ? g_bsum[idx] : 0;
        s += v[i];
    }
    int sc = s;
#pragma unroll
    for (int off = 1; off < 32; off <<= 1) {
        int t = __shfl_up_sync(0xFFFFFFFFu, sc, off);
        if (lane >= off) sc += t;
    }
    int run = sc - s;
#pragma unroll
    for (int i = 0; i < 4; i++) {
        int idx = lane * 4 + i;
        int t = v[i];
        if (idx < nb) g_bsum[idx] = run;
        run += t;
    }
    if (lane == 31) g_off[n] = run;
}

__global__ __launch_bounds__(256)
void scan3_kernel(int n) {
    int i = blockIdx.x * blockDim.x + threadIdx.x;
    if (i < n) g_off[i] += g_bsum[i >> 10];
}

__global__ __launch_bounds__(256)
void scatter_kernel(const int* __restrict__ ei, int E, int Etot) {
    int idx = blockIdx.x * blockDim.x + threadIdx.x;
    if (idx >= Etot) return;
    int s, d; load_edge(ei, E, idx, s, d);
    int pos = g_off[d] + atomicAdd(&g_cnt[d], 1);
    g_csr[pos] = s;
}

// ---------------- W1 convert: transpose + bf16 hi/lo split ----------------
__global__ __launch_bounds__(256)
void convw_kernel(const float* __restrict__ W1) {
    int idx = blockIdx.x * blockDim.x + threadIdx.x;   // 512*64
    if (idx >= 512 * 64) return;
    int n = idx & 63, k = idx >> 6;
    float w = W1[k * 64 + n];
    __nv_bfloat16 hi = __float2bfloat16(w);
    float lo = w - __bfloat162float(hi);
    g_w1h[n * 512 + k] = hi;
    g_w1l[n * 512 + k] = __float2bfloat16(lo);
}

// ---------------- GEMM1: mma.sync bf16x3-split + fused alpha1 ----------------
// CTA 128x64, BK=32, 8 warps (4m x 2n), warp tile 32x32.
// D = Ah*Bh + Ah*Bl + Al*Bh (lo*lo dropped, ~2^-16 relative).
// smem rows padded to 96 bytes (48 bf16).
#define PADB 96
#define OFF_AH 0
#define OFF_AL 12288
#define OFF_BH 24576
#define OFF_BL 30720
#define OFF_ATTS 36864
#define OFF_ATTD 37120
#define SM1_TOT  37376
#define CPAD 68

__global__ __launch_bounds__(256)
void gemm1_mma_kernel(const float* __restrict__ A, float* __restrict__ C, int M,
                      const float* __restrict__ att_s, const float* __restrict__ att_d) {
    extern __shared__ char sm[];
    float* Cs = (float*)sm;                       // reuses A/B space post-compute
    float* atts = (float*)(sm + OFF_ATTS);
    float* attd = (float*)(sm + OFF_ATTD);
    const int tid = threadIdx.x;
    const int wid = tid >> 5;
    const int lane = tid & 31;
    const int bm = blockIdx.x * 128;
    const int wm = (wid >> 1) * 32;               // warp m-base within tile
    const int wn = (wid & 1) * 32;                // warp n-base

    if (tid < 64) { atts[tid] = att_s[tid]; attd[tid] = att_d[tid]; }

    float d[2][4][4];
#pragma unroll
    for (int t = 0; t < 2; t++)
#pragma unroll
        for (int u = 0; u < 4; u++)
#pragma unroll
            for (int r = 0; r < 4; r++) d[t][u][r] = 0.f;

    // per-thread smem fill indices
    const int arow = tid >> 1;                    // 0..127
    const int ahalf = tid & 1;                    // 16-col half
    const int grow = bm + arow;
    const int bn = tid >> 2;                      // 0..63
    const int bq = (tid & 3) * 8;                 // k quarter (8 bf16)

    // ldmatrix addresses (bytes), ks*32 added per k-step
    const u32 sA = smem_u32(sm + OFF_AH);
    const u32 sB = smem_u32(sm + OFF_BH);
    u32 aAddr[2], bAddr[2];
#pragma unroll
    for (int t = 0; t < 2; t++)
        aAddr[t] = sA + (u32)((wm + t * 16 + ((lane >> 3) & 1) * 8 + (lane & 7)) * PADB
                              + ((lane >> 4) & 1) * 16);
#pragma unroll
    for (int p = 0; p < 2; p++)
        bAddr[p] = sB + (u32)((wn + p * 16 + ((lane >> 4) & 1) * 8 + (lane & 7)) * PADB
                              + ((lane >> 3) & 1) * 16);

    // prefetch tile 0
    float4 pa[4];
    uint4 pbh, pbl;
#pragma unroll
    for (int i = 0; i < 4; i++) {
        pa[i] = make_float4(0.f, 0.f, 0.f, 0.f);
        if (grow < M) pa[i] = *(const float4*)&A[(size_t)grow * 512 + ahalf * 16 + i * 4];
    }
    pbh = *(const uint4*)&g_w1h[bn * 512 + bq];
    pbl = *(const uint4*)&g_w1l[bn * 512 + bq];

    for (int kt = 0; kt < 16; kt++) {
        if (kt > 0) __syncthreads();   // previous compute must finish before overwrite

        // store A hi/lo (split) into smem
#pragma unroll
        for (int i = 0; i < 4; i++) {
            float4 v = pa[i];
            __nv_bfloat16 hx = __float2bfloat16(v.x), hy = __float2bfloat16(v.y);
            __nv_bfloat16 hz = __float2bfloat16(v.z), hw = __float2bfloat16(v.w);
            __nv_bfloat162 h01(hx, hy), h23(hz, hw);
            __nv_bfloat162 l01(__float2bfloat16(v.x - __bfloat162float(hx)),
                               __float2bfloat16(v.y - __bfloat162float(hy)));
            __nv_bfloat162 l23(__float2bfloat16(v.z - __bfloat162float(hz)),
                               __float2bfloat16(v.w - __bfloat162float(hw)));
            int off = arow * PADB + (ahalf * 16 + i * 4) * 2;
            *(uint2*)(sm + OFF_AH + off) = make_uint2(*(u32*)&h01, *(u32*)&h23);
            *(uint2*)(sm + OFF_AL + off) = make_uint2(*(u32*)&l01, *(u32*)&l23);
        }
        // store B hi/lo
        {
            int off = bn * PADB + bq * 2;
            *(uint4*)(sm + OFF_BH + off) = pbh;
            *(uint4*)(sm + OFF_BL + off) = pbl;
        }
        __syncthreads();

        // prefetch next tile while computing
        if (kt + 1 < 16) {
            int kb = (kt + 1) * 32;
#pragma unroll
            for (int i = 0; i < 4; i++) {
                pa[i] = make_float4(0.f, 0.f, 0.f, 0.f);
                if (grow < M)
                    pa[i] = *(const float4*)&A[(size_t)grow * 512 + kb + ahalf * 16 + i * 4];
            }
            pbh = *(const uint4*)&g_w1h[bn * 512 + kb + bq];
            pbl = *(const uint4*)&g_w1l[bn * 512 + kb + bq];
        }

#pragma unroll
        for (int ks = 0; ks < 2; ks++) {
            u32 ah[2][4], al[2][4], bh[2][4], bl[2][4];
#pragma unroll
            for (int t = 0; t < 2; t++) {
                ldm_x4(ah[t], aAddr[t] + ks * 32);
                ldm_x4(al[t], aAddr[t] + ks * 32 + (OFF_AL - OFF_AH));
            }
#pragma unroll
            for (int p = 0; p < 2; p++) {
                ldm_x4(bh[p], bAddr[p] + ks * 32);
                ldm_x4(bl[p], bAddr[p] + ks * 32 + (OFF_BL - OFF_BH));
            }
#pragma unroll
            for (int t = 0; t < 2; t++) {
#pragma unroll
                for (int u = 0; u < 4; u++) {
                    const u32* bhf = &bh[u >> 1][(u & 1) * 2];
                    const u32* blf = &bl[u >> 1][(u & 1) * 2];
                    mma_bf16(d[t][u], ah[t], bhf);
                    mma_bf16(d[t][u], ah[t], blf);
                    mma_bf16(d[t][u], al[t], bhf);
                }
            }
        }
    }

    // ---- epilogue: accumulators -> smem C tile (reuse A/B space) ----
    __syncthreads();
#pragma unroll
    for (int t = 0; t < 2; t++) {
#pragma unroll
        for (int u = 0; u < 4; u++) {
            int r0 = wm + t * 16 + (lane >> 2);
            int c  = wn + u * 8 + 2 * (lane & 3);
            *(float2*)&Cs[r0 * CPAD + c]       = make_float2(d[t][u][0], d[t][u][1]);
            *(float2*)&Cs[(r0 + 8) * CPAD + c] = make_float2(d[t][u][2], d[t][u][3]);
        }
    }
    __syncthreads();

    // ---- write h1 + fused alpha1: 2 threads per row, 32 cols each ----
    {
        int r = tid >> 1;
        int m = bm + r;
        int base = (tid & 1) * 32;     // cols base..base+31, heads base/8..+3
        if (m < M) {
            float as_acc[4] = {0.f, 0.f, 0.f, 0.f};
            float ad_acc[4] = {0.f, 0.f, 0.f, 0.f};
#pragma unroll
            for (int i = 0; i < 8; i++) {
                int c = base + i * 4;
                float4 v = *(const float4*)&Cs[r * CPAD + c];
                *(float4*)&g_h1[(size_t)m * 64 + c] = v;   // C == g_h1
                float4 sa = *(const float4*)&atts[c];
                float4 da = *(const float4*)&attd[c];
                int lh = i >> 1;
                as_acc[lh] += v.x * sa.x + v.y * sa.y + v.z * sa.z + v.w * sa.w;
                ad_acc[lh] += v.x * da.x + v.y * da.y + v.z * da.z + v.w * da.w;
            }
            int hb = (tid & 1) * 4;
            *(float4*)&g_as1[m * 8 + hb] = make_float4(as_acc[0], as_acc[1], as_acc[2], as_acc[3]);
            *(float4*)&g_ad1[m * 8 + hb] = make_float4(ad_acc[0], ad_acc[1], ad_acc[2], ad_acc[3]);
        }
    }
    (void)C;
}

// ---------------- GEMM2 (FFMA2 path) ----------------
__global__ __launch_bounds__(256)
void gemm_kernel(const float* __restrict__ A, const float* __restrict__ B,
                 float* __restrict__ C, int M, int K, int Ncol) {
    __shared__ float As[16][132];
    __shared__ float Bs[16][68];
    const int bm = blockIdx.x * 128;
    const int bn = blockIdx.y * 64;
    const int tid = threadIdx.x;
    const int tx = tid & 15;
    const int ty = tid >> 4;

    const int a_row  = tid >> 2;
    const int a_col4 = (tid & 3) * 4;
    const int b_row  = tid >> 4;
    const int b_col4 = (tid & 15) * 4;

    const int grow0 = bm + a_row;
    const int grow1 = bm + a_row + 64;

    u64 acc[4][4];
#pragma unroll
    for (int p = 0; p < 4; p++)
#pragma unroll
        for (int j = 0; j < 4; j++) acc[p][j] = 0ULL;

    float4 pa0 = make_float4(0.f,0.f,0.f,0.f), pa1 = pa0, pb;
    if (grow0 < M) pa0 = *(const float4*)&A[(size_t)grow0 * K + a_col4];
    if (grow1 < M) pa1 = *(const float4*)&A[(size_t)grow1 * K + a_col4];
    pb = *(const float4*)&B[(size_t)b_row * Ncol + bn + b_col4];

    for (int k0 = 0; k0 < K; k0 += 16) {
        As[a_col4 + 0][a_row] = pa0.x;
        As[a_col4 + 1][a_row] = pa0.y;
        As[a_col4 + 2][a_row] = pa0.z;
        As[a_col4 + 3][a_row] = pa0.w;
        As[a_col4 + 0][a_row + 64] = pa1.x;
        As[a_col4 + 1][a_row + 64] = pa1.y;
        As[a_col4 + 2][a_row + 64] = pa1.z;
        As[a_col4 + 3][a_row + 64] = pa1.w;
        *(float4*)&Bs[b_row][b_col4] = pb;
        __syncthreads();

        int kn = k0 + 16;
        if (kn < K) {
            if (grow0 < M) pa0 = *(const float4*)&A[(size_t)grow0 * K + kn + a_col4];
            if (grow1 < M) pa1 = *(const float4*)&A[(size_t)grow1 * K + kn + a_col4];
            pb = *(const float4*)&B[(size_t)(kn + b_row) * Ncol + bn + b_col4];
        }

#pragma unroll
        for (int kk = 0; kk < 16; kk++) {
            ulonglong2 A01 = *(const ulonglong2*)&As[kk][ty * 8];
            ulonglong2 A23 = *(const ulonglong2*)&As[kk][ty * 8 + 4];
            float4 b = *(const float4*)&Bs[kk][tx * 4];
            u64 b0 = pack2(b.x), b1 = pack2(b.y), b2 = pack2(b.z), b3 = pack2(b.w);
            ffma2(acc[0][0], A01.x, b0); ffma2(acc[0][1], A01.x, b1);
            ffma2(acc[0][2], A01.x, b2); ffma2(acc[0][3], A01.x, b3);
            ffma2(acc[1][0], A01.y, b0); ffma2(acc[1][1], A01.y, b1);
            ffma2(acc[1][2], A01.y, b2); ffma2(acc[1][3], A01.y, b3);
            ffma2(acc[2][0], A23.x, b0); ffma2(acc[2][1], A23.x, b1);
            ffma2(acc[2][2], A23.x, b2); ffma2(acc[2][3], A23.x, b3);
            ffma2(acc[3][0], A23.y, b0); ffma2(acc[3][1], A23.y, b1);
            ffma2(acc[3][2], A23.y, b2); ffma2(acc[3][3], A23.y, b3);
        }
        __syncthreads();
    }
#pragma unroll
    for (int p = 0; p < 4; p++) {
        float2 f0 = up2(acc[p][0]);
        float2 f1 = up2(acc[p][1]);
        float2 f2 = up2(acc[p][2]);
        float2 f3 = up2(acc[p][3]);
        int r0 = bm + ty * 8 + 2 * p;
        if (r0 < M)
            *(float4*)&C[(size_t)r0 * Ncol + bn + tx * 4] =
                make_float4(f0.x, f1.x, f2.x, f3.x);
        if (r0 + 1 < M)
            *(float4*)&C[(size_t)(r0 + 1) * Ncol + bn + tx * 4] =
                make_float4(f0.y, f1.y, f2.y, f3.y);
    }
}

// ---------------- layer2 alpha ----------------
__global__ __launch_bounds__(256)
void alpha2_kernel(const float* __restrict__ att_src, const float* __restrict__ att_dst,
                   int nnodes) {
    int gid = blockIdx.x * blockDim.x + threadIdx.x;
    int n = gid >> 5;
    int lane = gid & 31;
    if (n >= nnodes) return;
    float4 v = *(const float4*)&g_h2[(size_t)n * 128 + lane * 4];
    float4 a = ((const float4*)att_src)[lane];
    float4 b = ((const float4*)att_dst)[lane];
    float ss = v.x * a.x + v.y * a.y + v.z * a.z + v.w * a.w;
    float dd = v.x * b.x + v.y * b.y + v.z * b.z + v.w * b.w;
#pragma unroll
    for (int off = 16; off > 0; off >>= 1) {
        ss += __shfl_xor_sync(0xFFFFFFFFu, ss, off);
        dd += __shfl_xor_sync(0xFFFFFFFFu, dd, off);
    }
    if (lane == 0) { g_as2[n] = ss; g_ad2[n] = dd; }
}

// ---------------- aggregations ----------------
__global__ __launch_bounds__(256)
void agg1_kernel(const float* __restrict__ b1, int nnodes) {
    int gw = (blockIdx.x * 256 + threadIdx.x) >> 5;
    int lane = threadIdx.x & 31;
    if (gw >= nnodes) return;
    int h = lane >> 2;
    float ad = g_ad1[gw * 8 + h];
    int beg = g_off[gw], end = g_off[gw + 1];
    float ax = 0.f, ay = 0.f, denom = 0.f;
    int j = beg;
    for (; j + 4 <= end; j += 4) {
        int s0 = g_csr[j], s1 = g_csr[j + 1], s2 = g_csr[j + 2], s3 = g_csr[j + 3];
        float e0 = g_as1[s0 * 8 + h], e1 = g_as1[s1 * 8 + h];
        float e2 = g_as1[s2 * 8 + h], e3 = g_as1[s3 * 8 + h];
        float2 v0 = *(const float2*)&g_h1[s0 * 64 + lane * 2];
        float2 v1 = *(const float2*)&g_h1[s1 * 64 + lane * 2];
        float2 v2 = *(const float2*)&g_h1[s2 * 64 + lane * 2];
        float2 v3 = *(const float2*)&g_h1[s3 * 64 + lane * 2];
        float w0 = __expf(leaky(e0 + ad));
        float w1 = __expf(leaky(e1 + ad));
        float w2 = __expf(leaky(e2 + ad));
        float w3 = __expf(leaky(e3 + ad));
        ax += w0 * v0.x + w1 * v1.x + w2 * v2.x + w3 * v3.x;
        ay += w0 * v0.y + w1 * v1.y + w2 * v2.y + w3 * v3.y;
        denom += (w0 + w1) + (w2 + w3);
    }
    for (; j < end; j++) {
        int s = g_csr[j];
        float w = __expf(leaky(g_as1[s * 8 + h] + ad));
        float2 v = *(const float2*)&g_h1[s * 64 + lane * 2];
        ax += w * v.x; ay += w * v.y; denom += w;
    }
    float inv = 1.0f / denom;
    int c = lane * 2;
    float o0 = ax * inv + b1[c];
    float o1 = ay * inv + b1[c + 1];
    o0 = o0 > 0.f ? o0 : expm1f(o0);
    o1 = o1 > 0.f ? o1 : expm1f(o1);
    *(float2*)&g_hmid[gw * 64 + c] = make_float2(o0, o1);
}

__global__ __launch_bounds__(256)
void agg2_kernel(const float* __restrict__ b2, float* __restrict__ out, int nnodes) {
    int gw = (blockIdx.x * 256 + threadIdx.x) >> 5;
    int lane = threadIdx.x & 31;
    if (gw >= nnodes) return;
    float ad = g_ad2[gw];
    int beg = g_off[gw], end = g_off[gw + 1];
    float4 acc = make_float4(0.f, 0.f, 0.f, 0.f);
    float denom = 0.f;
    int j = beg;
    for (; j + 4 <= end; j += 4) {
        int s0 = g_csr[j], s1 = g_csr[j + 1], s2 = g_csr[j + 2], s3 = g_csr[j + 3];
        float e0 = g_as2[s0], e1 = g_as2[s1], e2 = g_as2[s2], e3 = g_as2[s3];
        float4 v0 = *(const float4*)&g_h2[(size_t)s0 * 128 + lane * 4];
        float4 v1 = *(const float4*)&g_h2[(size_t)s1 * 128 + lane * 4];
        float4 v2 = *(const float4*)&g_h2[(size_t)s2 * 128 + lane * 4];
        float4 v3 = *(const float4*)&g_h2[(size_t)s3 * 128 + lane * 4];
        float w0 = __expf(leaky(e0 + ad));
        float w1 = __expf(leaky(e1 + ad));
        float w2 = __expf(leaky(e2 + ad));
        float w3 = __expf(leaky(e3 + ad));
        acc.x += w0 * v0.x + w1 * v1.x + w2 * v2.x + w3 * v3.x;
        acc.y += w0 * v0.y + w1 * v1.y + w2 * v2.y + w3 * v3.y;
        acc.z += w0 * v0.z + w1 * v1.z + w2 * v2.z + w3 * v3.z;
        acc.w += w0 * v0.w + w1 * v1.w + w2 * v2.w + w3 * v3.w;
        denom += (w0 + w1) + (w2 + w3);
    }
    for (; j < end; j++) {
        int s = g_csr[j];
        float w = __expf(leaky(g_as2[s] + ad));
        float4 v = *(const float4*)&g_h2[(size_t)s * 128 + lane * 4];
        acc.x += w * v.x; acc.y += w * v.y; acc.z += w * v.z; acc.w += w * v.w;
        denom += w;
    }
    float inv = 1.0f / denom;
    float4 bb = ((const float4*)b2)[lane];
    float4 o = make_float4(acc.x * inv + bb.x, acc.y * inv + bb.y,
                           acc.z * inv + bb.z, acc.w * inv + bb.w);
    *(float4*)&out[(size_t)gw * 128 + lane * 4] = o;
}

// ---------------- launcher ----------------
static cudaStream_t g_side = nullptr;
static cudaEvent_t  g_ev_fork = nullptr, g_ev_csr = nullptr;

extern "C" void kernel_launch(void* const* d_in, const int* in_sizes, int n_in,
                              void* d_out, int out_size) {
    const float* x        = (const float*)d_in[0];
    const int*   ei       = (const int*)d_in[1];
    const float* W1       = (const float*)d_in[2];
    const float* att_src1 = (const float*)d_in[3];
    const float* att_dst1 = (const float*)d_in[4];
    const float* b1       = (const float*)d_in[5];
    const float* W2       = (const float*)d_in[6];
    const float* att_src2 = (const float*)d_in[7];
    const float* att_dst2 = (const float*)d_in[8];
    const float* b2       = (const float*)d_in[9];
    float* out = (float*)d_out;

    const int nnodes = in_sizes[0] / 512;
    const int E      = in_sizes[1] / 2;
    const int Etot   = E + nnodes;
    const int T = 256;
    const int NB = (nnodes + 1023) / 1024;

    if (!g_side) {
        cudaStreamCreateWithFlags(&g_side, cudaStreamNonBlocking);
        cudaEventCreateWithFlags(&g_ev_fork, cudaEventDisableTiming);
        cudaEventCreateWithFlags(&g_ev_csr,  cudaEventDisableTiming);
        cudaFuncSetAttribute(gemm1_mma_kernel,
                             cudaFuncAttributeMaxDynamicSharedMemorySize, SM1_TOT);
    }

    void* pcnt; cudaGetSymbolAddress(&pcnt, g_cnt);
    float *h1_ptr, *hmid_ptr, *h2_ptr;
    cudaGetSymbolAddress((void**)&h1_ptr, g_h1);
    cudaGetSymbolAddress((void**)&hmid_ptr, g_hmid);
    cudaGetSymbolAddress((void**)&h2_ptr, g_h2);

    // fork side stream for CSR build
    cudaEventRecord(g_ev_fork, 0);
    cudaStreamWaitEvent(g_side, g_ev_fork, 0);

    convw_kernel<<<(512 * 64 + T - 1) / T, T>>>(W1);                     // k1 (main)
    cudaMemsetAsync(pcnt, 0, (size_t)nnodes * 4, g_side);
    hist_kernel<<<(Etot + T - 1) / T, T, 0, g_side>>>(ei, E, Etot);      // k2
    scan1_kernel<<<NB, T, 0, g_side>>>(nnodes);                          // k3

    gemm1_mma_kernel<<<(nnodes + 127) / 128, T, SM1_TOT>>>(x, h1_ptr, nnodes,  // k4 (profiled)
                                                           att_src1, att_dst1);

    scan2_kernel<<<1, 32, 0, g_side>>>(NB, nnodes);                      // k5
    scan3_kernel<<<(nnodes + T - 1) / T, T, 0, g_side>>>(nnodes);        // k6
    cudaMemsetAsync(pcnt, 0, (size_t)nnodes * 4, g_side);
    scatter_kernel<<<(Etot + T - 1) / T, T, 0, g_side>>>(ei, E, Etot);   // k7
    cudaEventRecord(g_ev_csr, g_side);

    cudaStreamWaitEvent(0, g_ev_csr, 0);
    agg1_kernel<<<((size_t)nnodes * 32 + T - 1) / T, T>>>(b1, nnodes);   // k8

    dim3 g2grid((nnodes + 127) / 128, 2);
    gemm_kernel<<<g2grid, T>>>(hmid_ptr, W2, h2_ptr, nnodes, 64, 128);   // k9
    alpha2_kernel<<<((size_t)nnodes * 32 + T - 1) / T, T>>>(att_src2, att_dst2, nnodes); // k10
    agg2_kernel<<<((size_t)nnodes * 32 + T - 1) / T, T>>>(b2, out, nnodes);   // k11
}

// round 14
// speedup vs baseline: 1.2305x; 1.0805x over previous
#include <cuda_runtime.h>
#include <cuda_bf16.h>
#include <cstdint>
#include <math.h>

#define NN 100000
#define EMAX 1700000
#define NEG_SLOPE 0.2f

typedef unsigned long long u64;
typedef unsigned int u32;

// ---------------- scratch (device globals) ----------------
__device__ __align__(16) float g_h1[NN * 64];
__device__ __align__(16) float g_as1[NN * 8];
__device__ __align__(16) float g_ad1[NN * 8];
__device__ __align__(16) float g_hmid[NN * 64];
__device__ __align__(16) float g_h2[NN * 128];
__device__ __align__(16) float g_as2[NN];
__device__ __align__(16) float g_ad2[NN];
// W1 in mma-fragment-packed layout: [32 kblocks][8 nblocks][32 lanes] x uint4
// uint4 = {b0_hi, b1_hi, b0_lo, b1_lo} (bf16x2 pairs, hi/lo split)
__device__ __align__(16) uint4 g_w1f[32 * 8 * 32];
// CSR by destination
__device__ int g_cnt[NN];
__device__ int g_off[NN + 1];
__device__ int g_bsum[128];
__device__ int g_csr[EMAX];

// ---------------- helpers ----------------
__device__ __forceinline__ float leaky(float v) {
    return v > 0.0f ? v : NEG_SLOPE * v;
}
__device__ __forceinline__ void load_edge(const int* __restrict__ ei, int E,
                                          int idx, int& s, int& d) {
    if (idx < E) { s = ei[idx]; d = ei[E + idx]; }
    else         { s = d = idx - E; }
}
__device__ __forceinline__ u64 pack2(float v) {
    u64 r; asm("mov.b64 %0, {%1, %1};" : "=l"(r) : "f"(v)); return r;
}
__device__ __forceinline__ void ffma2(u64& acc, u64 a, u64 b) {
    asm("fma.rn.f32x2 %0, %1, %2, %3;" : "=l"(acc) : "l"(a), "l"(b), "l"(acc));
}
__device__ __forceinline__ float2 up2(u64 v) { return *(float2*)&v; }

// pack 2 floats -> bf16x2 hi pair + bf16x2 lo (residual) pair.
// low half of result = first element (v.x), matching a0={A[g][2t],A[g][2t+1]}.
__device__ __forceinline__ void cvt_hilo(float2 v, u32& hi, u32& lo) {
    u32 h;
    asm("cvt.rn.bf16x2.f32 %0, %1, %2;" : "=r"(h) : "f"(v.y), "f"(v.x));
    float xf = __uint_as_float(h << 16);
    float yf = __uint_as_float(h & 0xFFFF0000u);
    float lx = v.x - xf;
    float ly = v.y - yf;
    u32 l;
    asm("cvt.rn.bf16x2.f32 %0, %1, %2;" : "=r"(l) : "f"(ly), "f"(lx));
    hi = h; lo = l;
}

__device__ __forceinline__ void mma_bf16(float* d, const u32* a, u32 b0, u32 b1) {
    asm volatile(
        "mma.sync.aligned.m16n8k16.row.col.f32.bf16.bf16.f32 "
        "{%0,%1,%2,%3}, {%4,%5,%6,%7}, {%8,%9}, {%0,%1,%2,%3};"
        : "+f"(d[0]), "+f"(d[1]), "+f"(d[2]), "+f"(d[3])
        : "r"(a[0]), "r"(a[1]), "r"(a[2]), "r"(a[3]), "r"(b0), "r"(b1));
}

// ---------------- CSR build ----------------
__global__ __launch_bounds__(256)
void hist_kernel(const int* __restrict__ ei, int E, int Etot) {
    int idx = blockIdx.x * blockDim.x + threadIdx.x;
    if (idx >= Etot) return;
    int s, d; load_edge(ei, E, idx, s, d);
    atomicAdd(&g_cnt[d], 1);
}

__global__ __launch_bounds__(256)
void scan1_kernel(int n) {
    __shared__ int wsum[8];
    int blk = blockIdx.x;
    int tid = threadIdx.x;
    int i = blk * 1024 + tid * 4;
    int a0 = (i + 0 < n) ? g_cnt[i + 0] : 0;
    int a1 = (i + 1 < n) ? g_cnt[i + 1] : 0;
    int a2 = (i + 2 < n) ? g_cnt[i + 2] : 0;
    int a3 = (i + 3 < n) ? g_cnt[i + 3] : 0;
    int tsum = a0 + a1 + a2 + a3;
    int lane = tid & 31, wid = tid >> 5;
    int sc = tsum;
#pragma unroll
    for (int off = 1; off < 32; off <<= 1) {
        int t = __shfl_up_sync(0xFFFFFFFFu, sc, off);
        if (lane >= off) sc += t;
    }
    if (lane == 31) wsum[wid] = sc;
    __syncthreads();
    if (wid == 0) {
        int ws = (lane < 8) ? wsum[lane] : 0;
#pragma unroll
        for (int off = 1; off < 8; off <<= 1) {
            int t = __shfl_up_sync(0xFFFFFFFFu, ws, off);
            if (lane >= off) ws += t;
        }
        if (lane < 8) wsum[lane] = ws;
    }
    __syncthreads();
    int excl = sc - tsum + (wid > 0 ? wsum[wid - 1] : 0);
    if (i + 0 < n) g_off[i + 0] = excl;
    if (i + 1 < n) g_off[i + 1] = excl + a0;
    if (i + 2 < n) g_off[i + 2] = excl + a0 + a1;
    if (i + 3 < n) g_off[i + 3] = excl + a0 + a1 + a2;
    if (tid == 255) g_bsum[blk] = excl + tsum;
}

__global__ void scan2_kernel(int nb, int n) {
    int lane = threadIdx.x & 31;
    int v[4]; int s = 0;
#pragma unroll
    for (int i = 0; i < 4; i++) {
        int idx = lane * 4 + i;
        v[i] = (idx < nb) ? g_bsum[idx] : 0;
        s += v[i];
    }
    int sc = s;
#pragma unroll
    for (int off = 1; off < 32; off <<= 1) {
        int t = __shfl_up_sync(0xFFFFFFFFu, sc, off);
        if (lane >= off) sc += t;
    }
    int run = sc - s;
#pragma unroll
    for (int i = 0; i < 4; i++) {
        int idx = lane * 4 + i;
        int t = v[i];
        if (idx < nb) g_bsum[idx] = run;
        run += t;
    }
    if (lane == 31) g_off[n] = run;
}

__global__ __launch_bounds__(256)
void scan3_kernel(int n) {
    int i = blockIdx.x * blockDim.x + threadIdx.x;
    if (i < n) g_off[i] += g_bsum[i >> 10];
}

__global__ __launch_bounds__(256)
void scatter_kernel(const int* __restrict__ ei, int E, int Etot) {
    int idx = blockIdx.x * blockDim.x + threadIdx.x;
    if (idx >= Etot) return;
    int s, d; load_edge(ei, E, idx, s, d);
    int pos = g_off[d] + atomicAdd(&g_cnt[d], 1);
    g_csr[pos] = s;
}

// ---------------- W1 convert: mma-fragment packing with hi/lo split ----------
// One thread per (kblock, nblock, lane): 32*8*32 = 8192 threads.
__global__ __launch_bounds__(256)
void convw_kernel(const float* __restrict__ W1) {
    int idx = blockIdx.x * blockDim.x + threadIdx.x;
    if (idx >= 32 * 8 * 32) return;
    int l  = idx & 31;
    int nb = (idx >> 5) & 7;
    int kb = idx >> 8;
    int n = nb * 8 + (l >> 2);
    int k = kb * 16 + 2 * (l & 3);
    float w00 = W1[(size_t)k * 64 + n];
    float w01 = W1[(size_t)(k + 1) * 64 + n];
    float w10 = W1[(size_t)(k + 8) * 64 + n];
    float w11 = W1[(size_t)(k + 9) * 64 + n];
    u32 b0h, b0l, b1h, b1l;
    cvt_hilo(make_float2(w00, w01), b0h, b0l);
    cvt_hilo(make_float2(w10, w11), b1h, b1l);
    g_w1f[idx] = make_uint4(b0h, b1h, b0l, b1l);
}

// ---------------- GEMM1: register-direct mma.sync bf16x3-split + alpha1 ------
// CTA 128x64, 8 warps (4m x 2n), warp tile 32x32. NO smem in mainloop:
// A fragments loaded as fp32 pairs via LDG.64 and split in registers,
// B fragments via one LDG.128 from the prepacked table.
#define CPAD 68
#define OFF_ATTS (128 * CPAD * 4)
#define OFF_ATTD (OFF_ATTS + 256)
#define SM1_TOT  (OFF_ATTD + 256)

__global__ __launch_bounds__(256)
void gemm1_mma_kernel(const float* __restrict__ A, int M,
                      const float* __restrict__ att_s, const float* __restrict__ att_d) {
    extern __shared__ char sm[];
    float* Cs = (float*)sm;
    float* atts = (float*)(sm + OFF_ATTS);
    float* attd = (float*)(sm + OFF_ATTD);
    const int tid = threadIdx.x;
    const int wid = tid >> 5;
    const int lane = tid & 31;
    const int bm = blockIdx.x * 128;
    const int wm = (wid >> 1) * 32;
    const int nb4 = (wid & 1) * 4;      // first n-block of this warp (of 8)

    if (tid < 64) { atts[tid] = att_s[tid]; attd[tid] = att_d[tid]; }

    float d[2][4][4];
#pragma unroll
    for (int t = 0; t < 2; t++)
#pragma unroll
        for (int u = 0; u < 4; u++)
#pragma unroll
            for (int r = 0; r < 4; r++) d[t][u][r] = 0.f;

    // 4 row pointers: rows wm + {0,8,16,24} + (lane>>2), clamped (OOB rows discarded later)
    const int g = lane >> 2;
    const int t2 = 2 * (lane & 3);
    const float* pr[4];
#pragma unroll
    for (int i = 0; i < 4; i++) {
        int r = bm + wm + i * 8 + g;
        if (r > M - 1) r = M - 1;
        pr[i] = A + (size_t)r * 512 + t2;
    }
    const uint4* pB = g_w1f + nb4 * 32 + lane;

    for (int kt = 0; kt < 32; kt++) {       // 32 x k16 steps
        const int k0 = kt * 16;
        u32 ah[2][4], al[2][4];
#pragma unroll
        for (int t = 0; t < 2; t++) {
            float2 x0 = *(const float2*)(pr[2 * t]     + k0);
            float2 x1 = *(const float2*)(pr[2 * t + 1] + k0);
            float2 x2 = *(const float2*)(pr[2 * t]     + k0 + 8);
            float2 x3 = *(const float2*)(pr[2 * t + 1] + k0 + 8);
            cvt_hilo(x0, ah[t][0], al[t][0]);
            cvt_hilo(x1, ah[t][1], al[t][1]);
            cvt_hilo(x2, ah[t][2], al[t][2]);
            cvt_hilo(x3, ah[t][3], al[t][3]);
        }
        uint4 bf0 = pB[(kt * 8 + 0) * 32];
        uint4 bf1 = pB[(kt * 8 + 1) * 32];
        uint4 bf2 = pB[(kt * 8 + 2) * 32];
        uint4 bf3 = pB[(kt * 8 + 3) * 32];
#pragma unroll
        for (int t = 0; t < 2; t++) {
            mma_bf16(d[t][0], ah[t], bf0.x, bf0.y);
            mma_bf16(d[t][0], ah[t], bf0.z, bf0.w);
            mma_bf16(d[t][0], al[t], bf0.x, bf0.y);
            mma_bf16(d[t][1], ah[t], bf1.x, bf1.y);
            mma_bf16(d[t][1], ah[t], bf1.z, bf1.w);
            mma_bf16(d[t][1], al[t], bf1.x, bf1.y);
            mma_bf16(d[t][2], ah[t], bf2.x, bf2.y);
            mma_bf16(d[t][2], ah[t], bf2.z, bf2.w);
            mma_bf16(d[t][2], al[t], bf2.x, bf2.y);
            mma_bf16(d[t][3], ah[t], bf3.x, bf3.y);
            mma_bf16(d[t][3], ah[t], bf3.z, bf3.w);
            mma_bf16(d[t][3], al[t], bf3.x, bf3.y);
        }
    }

    // ---- epilogue: accumulators -> smem C tile ----
    const int wn = (wid & 1) * 32;
    __syncthreads();
#pragma unroll
    for (int t = 0; t < 2; t++) {
#pragma unroll
        for (int u = 0; u < 4; u++) {
            int r0 = wm + t * 16 + g;
            int c  = wn + u * 8 + t2;
            *(float2*)&Cs[r0 * CPAD + c]       = make_float2(d[t][u][0], d[t][u][1]);
            *(float2*)&Cs[(r0 + 8) * CPAD + c] = make_float2(d[t][u][2], d[t][u][3]);
        }
    }
    __syncthreads();

    // ---- write h1 + fused alpha1: 2 threads per row, 32 cols each ----
    {
        int r = tid >> 1;
        int m = bm + r;
        int base = (tid & 1) * 32;
        if (m < M) {
            float as_acc[4] = {0.f, 0.f, 0.f, 0.f};
            float ad_acc[4] = {0.f, 0.f, 0.f, 0.f};
#pragma unroll
            for (int i = 0; i < 8; i++) {
                int c = base + i * 4;
                float4 v = *(const float4*)&Cs[r * CPAD + c];
                *(float4*)&g_h1[(size_t)m * 64 + c] = v;
                float4 sa = *(const float4*)&atts[c];
                float4 da = *(const float4*)&attd[c];
                int lh = i >> 1;
                as_acc[lh] += v.x * sa.x + v.y * sa.y + v.z * sa.z + v.w * sa.w;
                ad_acc[lh] += v.x * da.x + v.y * da.y + v.z * da.z + v.w * da.w;
            }
            int hb = (tid & 1) * 4;
            *(float4*)&g_as1[m * 8 + hb] = make_float4(as_acc[0], as_acc[1], as_acc[2], as_acc[3]);
            *(float4*)&g_ad1[m * 8 + hb] = make_float4(ad_acc[0], ad_acc[1], ad_acc[2], ad_acc[3]);
        }
    }
}

// ---------------- GEMM2 (FFMA2 path) ----------------
__global__ __launch_bounds__(256)
void gemm_kernel(const float* __restrict__ A, const float* __restrict__ B,
                 float* __restrict__ C, int M, int K, int Ncol) {
    __shared__ float As[16][132];
    __shared__ float Bs[16][68];
    const int bm = blockIdx.x * 128;
    const int bn = blockIdx.y * 64;
    const int tid = threadIdx.x;
    const int tx = tid & 15;
    const int ty = tid >> 4;

    const int a_row  = tid >> 2;
    const int a_col4 = (tid & 3) * 4;
    const int b_row  = tid >> 4;
    const int b_col4 = (tid & 15) * 4;

    const int grow0 = bm + a_row;
    const int grow1 = bm + a_row + 64;

    u64 acc[4][4];
#pragma unroll
    for (int p = 0; p < 4; p++)
#pragma unroll
        for (int j = 0; j < 4; j++) acc[p][j] = 0ULL;

    float4 pa0 = make_float4(0.f,0.f,0.f,0.f), pa1 = pa0, pb;
    if (grow0 < M) pa0 = *(const float4*)&A[(size_t)grow0 * K + a_col4];
    if (grow1 < M) pa1 = *(const float4*)&A[(size_t)grow1 * K + a_col4];
    pb = *(const float4*)&B[(size_t)b_row * Ncol + bn + b_col4];

    for (int k0 = 0; k0 < K; k0 += 16) {
        As[a_col4 + 0][a_row] = pa0.x;
        As[a_col4 + 1][a_row] = pa0.y;
        As[a_col4 + 2][a_row] = pa0.z;
        As[a_col4 + 3][a_row] = pa0.w;
        As[a_col4 + 0][a_row + 64] = pa1.x;
        As[a_col4 + 1][a_row + 64] = pa1.y;
        As[a_col4 + 2][a_row + 64] = pa1.z;
        As[a_col4 + 3][a_row + 64] = pa1.w;
        *(float4*)&Bs[b_row][b_col4] = pb;
        __syncthreads();

        int kn = k0 + 16;
        if (kn < K) {
            if (grow0 < M) pa0 = *(const float4*)&A[(size_t)grow0 * K + kn + a_col4];
            if (grow1 < M) pa1 = *(const float4*)&A[(size_t)grow1 * K + kn + a_col4];
            pb = *(const float4*)&B[(size_t)(kn + b_row) * Ncol + bn + b_col4];
        }

#pragma unroll
        for (int kk = 0; kk < 16; kk++) {
            ulonglong2 A01 = *(const ulonglong2*)&As[kk][ty * 8];
            ulonglong2 A23 = *(const ulonglong2*)&As[kk][ty * 8 + 4];
            float4 b = *(const float4*)&Bs[kk][tx * 4];
            u64 b0 = pack2(b.x), b1 = pack2(b.y), b2 = pack2(b.z), b3 = pack2(b.w);
            ffma2(acc[0][0], A01.x, b0); ffma2(acc[0][1], A01.x, b1);
            ffma2(acc[0][2], A01.x, b2); ffma2(acc[0][3], A01.x, b3);
            ffma2(acc[1][0], A01.y, b0); ffma2(acc[1][1], A01.y, b1);
            ffma2(acc[1][2], A01.y, b2); ffma2(acc[1][3], A01.y, b3);
            ffma2(acc[2][0], A23.x, b0); ffma2(acc[2][1], A23.x, b1);
            ffma2(acc[2][2], A23.x, b2); ffma2(acc[2][3], A23.x, b3);
            ffma2(acc[3][0], A23.y, b0); ffma2(acc[3][1], A23.y, b1);
            ffma2(acc[3][2], A23.y, b2); ffma2(acc[3][3], A23.y, b3);
        }
        __syncthreads();
    }
#pragma unroll
    for (int p = 0; p < 4; p++) {
        float2 f0 = up2(acc[p][0]);
        float2 f1 = up2(acc[p][1]);
        float2 f2 = up2(acc[p][2]);
        float2 f3 = up2(acc[p][3]);
        int r0 = bm + ty * 8 + 2 * p;
        if (r0 < M)
            *(float4*)&C[(size_t)r0 * Ncol + bn + tx * 4] =
                make_float4(f0.x, f1.x, f2.x, f3.x);
        if (r0 + 1 < M)
            *(float4*)&C[(size_t)(r0 + 1) * Ncol + bn + tx * 4] =
                make_float4(f0.y, f1.y, f2.y, f3.y);
    }
}

// ---------------- layer2 alpha ----------------
__global__ __launch_bounds__(256)
void alpha2_kernel(const float* __restrict__ att_src, const float* __restrict__ att_dst,
                   int nnodes) {
    int gid = blockIdx.x * blockDim.x + threadIdx.x;
    int n = gid >> 5;
    int lane = gid & 31;
    if (n >= nnodes) return;
    float4 v = *(const float4*)&g_h2[(size_t)n * 128 + lane * 4];
    float4 a = ((const float4*)att_src)[lane];
    float4 b = ((const float4*)att_dst)[lane];
    float ss = v.x * a.x + v.y * a.y + v.z * a.z + v.w * a.w;
    float dd = v.x * b.x + v.y * b.y + v.z * b.z + v.w * b.w;
#pragma unroll
    for (int off = 16; off > 0; off >>= 1) {
        ss += __shfl_xor_sync(0xFFFFFFFFu, ss, off);
        dd += __shfl_xor_sync(0xFFFFFFFFu, dd, off);
    }
    if (lane == 0) { g_as2[n] = ss; g_ad2[n] = dd; }
}

// ---------------- aggregations ----------------
__global__ __launch_bounds__(256)
void agg1_kernel(const float* __restrict__ b1, int nnodes) {
    int gw = (blockIdx.x * 256 + threadIdx.x) >> 5;
    int lane = threadIdx.x & 31;
    if (gw >= nnodes) return;
    int h = lane >> 2;
    float ad = g_ad1[gw * 8 + h];
    int beg = g_off[gw], end = g_off[gw + 1];
    float ax = 0.f, ay = 0.f, denom = 0.f;
    int j = beg;
    for (; j + 4 <= end; j += 4) {
        int s0 = g_csr[j], s1 = g_csr[j + 1], s2 = g_csr[j + 2], s3 = g_csr[j + 3];
        float e0 = g_as1[s0 * 8 + h], e1 = g_as1[s1 * 8 + h];
        float e2 = g_as1[s2 * 8 + h], e3 = g_as1[s3 * 8 + h];
        float2 v0 = *(const float2*)&g_h1[s0 * 64 + lane * 2];
        float2 v1 = *(const float2*)&g_h1[s1 * 64 + lane * 2];
        float2 v2 = *(const float2*)&g_h1[s2 * 64 + lane * 2];
        float2 v3 = *(const float2*)&g_h1[s3 * 64 + lane * 2];
        float w0 = __expf(leaky(e0 + ad));
        float w1 = __expf(leaky(e1 + ad));
        float w2 = __expf(leaky(e2 + ad));
        float w3 = __expf(leaky(e3 + ad));
        ax += w0 * v0.x + w1 * v1.x + w2 * v2.x + w3 * v3.x;
        ay += w0 * v0.y + w1 * v1.y + w2 * v2.y + w3 * v3.y;
        denom += (w0 + w1) + (w2 + w3);
    }
    for (; j < end; j++) {
        int s = g_csr[j];
        float w = __expf(leaky(g_as1[s * 8 + h] + ad));
        float2 v = *(const float2*)&g_h1[s * 64 + lane * 2];
        ax += w * v.x; ay += w * v.y; denom += w;
    }
    float inv = 1.0f / denom;
    int c = lane * 2;
    float o0 = ax * inv + b1[c];
    float o1 = ay * inv + b1[c + 1];
    o0 = o0 > 0.f ? o0 : expm1f(o0);
    o1 = o1 > 0.f ? o1 : expm1f(o1);
    *(float2*)&g_hmid[gw * 64 + c] = make_float2(o0, o1);
}

__global__ __launch_bounds__(256)
void agg2_kernel(const float* __restrict__ b2, float* __restrict__ out, int nnodes) {
    int gw = (blockIdx.x * 256 + threadIdx.x) >> 5;
    int lane = threadIdx.x & 31;
    if (gw >= nnodes) return;
    float ad = g_ad2[gw];
    int beg = g_off[gw], end = g_off[gw + 1];
    float4 acc = make_float4(0.f, 0.f, 0.f, 0.f);
    float denom = 0.f;
    int j = beg;
    for (; j + 4 <= end; j += 4) {
        int s0 = g_csr[j], s1 = g_csr[j + 1], s2 = g_csr[j + 2], s3 = g_csr[j + 3];
        float e0 = g_as2[s0], e1 = g_as2[s1], e2 = g_as2[s2], e3 = g_as2[s3];
        float4 v0 = *(const float4*)&g_h2[(size_t)s0 * 128 + lane * 4];
        float4 v1 = *(const float4*)&g_h2[(size_t)s1 * 128 + lane * 4];
        float4 v2 = *(const float4*)&g_h2[(size_t)s2 * 128 + lane * 4];
        float4 v3 = *(const float4*)&g_h2[(size_t)s3 * 128 + lane * 4];
        float w0 = __expf(leaky(e0 + ad));
        float w1 = __expf(leaky(e1 + ad));
        float w2 = __expf(leaky(e2 + ad));
        float w3 = __expf(leaky(e3 + ad));
        acc.x += w0 * v0.x + w1 * v1.x + w2 * v2.x + w3 * v3.x;
        acc.y += w0 * v0.y + w1 * v1.y + w2 * v2.y + w3 * v3.y;
        acc.z += w0 * v0.z + w1 * v1.z + w2 * v2.z + w3 * v3.z;
        acc.w += w0 * v0.w + w1 * v1.w + w2 * v2.w + w3 * v3.w;
        denom += (w0 + w1) + (w2 + w3);
    }
    for (; j < end; j++) {
        int s = g_csr[j];
        float w = __expf(leaky(g_as2[s] + ad));
        float4 v = *(const float4*)&g_h2[(size_t)s * 128 + lane * 4];
        acc.x += w * v.x; acc.y += w * v.y; acc.z += w * v.z; acc.w += w * v.w;
        denom += w;
    }
    float inv = 1.0f / denom;
    float4 bb = ((const float4*)b2)[lane];
    float4 o = make_float4(acc.x * inv + bb.x, acc.y * inv + bb.y,
                           acc.z * inv + bb.z, acc.w * inv + bb.w);
    *(float4*)&out[(size_t)gw * 128 + lane * 4] = o;
}

// ---------------- launcher ----------------
static cudaStream_t g_side = nullptr;
static cudaEvent_t  g_ev_fork = nullptr, g_ev_csr = nullptr;

extern "C" void kernel_launch(void* const* d_in, const int* in_sizes, int n_in,
                              void* d_out, int out_size) {
    const float* x        = (const float*)d_in[0];
    const int*   ei       = (const int*)d_in[1];
    const float* W1       = (const float*)d_in[2];
    const float* att_src1 = (const float*)d_in[3];
    const float* att_dst1 = (const float*)d_in[4];
    const float* b1       = (const float*)d_in[5];
    const float* W2       = (const float*)d_in[6];
    const float* att_src2 = (const float*)d_in[7];
    const float* att_dst2 = (const float*)d_in[8];
    const float* b2       = (const float*)d_in[9];
    float* out = (float*)d_out;

    const int nnodes = in_sizes[0] / 512;
    const int E      = in_sizes[1] / 2;
    const int Etot   = E + nnodes;
    const int T = 256;
    const int NB = (nnodes + 1023) / 1024;

    if (!g_side) {
        cudaStreamCreateWithFlags(&g_side, cudaStreamNonBlocking);
        cudaEventCreateWithFlags(&g_ev_fork, cudaEventDisableTiming);
        cudaEventCreateWithFlags(&g_ev_csr,  cudaEventDisableTiming);
        cudaFuncSetAttribute(gemm1_mma_kernel,
                             cudaFuncAttributeMaxDynamicSharedMemorySize, SM1_TOT);
    }

    void* pcnt; cudaGetSymbolAddress(&pcnt, g_cnt);
    float *h1_ptr, *hmid_ptr, *h2_ptr;
    cudaGetSymbolAddress((void**)&h1_ptr, g_h1);
    cudaGetSymbolAddress((void**)&hmid_ptr, g_hmid);
    cudaGetSymbolAddress((void**)&h2_ptr, g_h2);

    // fork side stream for CSR build
    cudaEventRecord(g_ev_fork, 0);
    cudaStreamWaitEvent(g_side, g_ev_fork, 0);

    convw_kernel<<<32, T>>>(W1);                                         // k1 (main)
    cudaMemsetAsync(pcnt, 0, (size_t)nnodes * 4, g_side);
    hist_kernel<<<(Etot + T - 1) / T, T, 0, g_side>>>(ei, E, Etot);      // k2
    scan1_kernel<<<NB, T, 0, g_side>>>(nnodes);                          // k3

    gemm1_mma_kernel<<<(nnodes + 127) / 128, T, SM1_TOT>>>(x, nnodes,    // k4 (profiled)
                                                           att_src1, att_dst1);

    scan2_kernel<<<1, 32, 0, g_side>>>(NB, nnodes);                      // k5
    scan3_kernel<<<(nnodes + T - 1) / T, T, 0, g_side>>>(nnodes);        // k6
    cudaMemsetAsync(pcnt, 0, (size_t)nnodes * 4, g_side);
    scatter_kernel<<<(Etot + T - 1) / T, T, 0, g_side>>>(ei, E, Etot);   // k7
    cudaEventRecord(g_ev_csr, g_side);

    cudaStreamWaitEvent(0, g_ev_csr, 0);
    agg1_kernel<<<((size_t)nnodes * 32 + T - 1) / T, T>>>(b1, nnodes);   // k8

    dim3 g2grid((nnodes + 127) / 128, 2);
    gemm_kernel<<<g2grid, T>>>(hmid_ptr, W2, h2_ptr, nnodes, 64, 128);   // k9
    alpha2_kernel<<<((size_t)nnodes * 32 + T - 1) / T, T>>>(att_src2, att_dst2, nnodes); // k10
    agg2_kernel<<<((size_t)nnodes * 32 + T - 1) / T, T>>>(b2, out, nnodes);   // k11
}